// round 1
// baseline (speedup 1.0000x reference)
#include <cuda_runtime.h>
#include <cstdint>

#define B_      64
#define CIN     64
#define COUT    64
#define IMG     32
#define POS     1024        // IMG*IMG
#define KC      36          // 4 channels * 9 taps per K-chunk
#define NCHUNK  16          // 64 channels / 4

// scratch: y (pre-BN) in transposed layout [o][pos][b], plus per-channel stats
__device__ float g_yt[(size_t)COUT * POS * B_];
__device__ float g_sum[COUT];
__device__ float g_sumsq[COUT];

// -------------------- Phase 1: per-position GEMM + bias --------------------
// block = one spatial position; tile M=64(b) x N=64(o), K=576 in 16 chunks of 36.
// 128 threads, each computes a 4(b) x 8(o) microtile.
__global__ __launch_bounds__(128, 4)
void ll_gemm_kernel(const float* __restrict__ x,
                    const float* __restrict__ w,
                    const float* __restrict__ bias)
{
    __shared__ float sA[2][KC][B_];     // [k][b]
    __shared__ float sB[2][KC][COUT];   // [k][o]

    const int pos = blockIdx.x;
    const int i = pos >> 5;
    const int j = pos & 31;
    const int t = threadIdx.x;
    const int tb = t & 15;              // b-group (4 rows each)
    const int to = t >> 4;              // o-group (8 cols each)

    float acc[4][8];
#pragma unroll
    for (int m = 0; m < 4; ++m)
#pragma unroll
        for (int n = 0; n < 8; ++n) acc[m][n] = 0.f;

    float rA[2][9], rB[2][9];

    // ---- prologue: load chunk 0 straight into smem buffer 0 ----
#pragma unroll
    for (int idx = 0; idx < 2; ++idx) {
        const int lin = t + idx * 128;          // 0..255 -> 64 (b|o) x 4 c'
        const int bb  = lin & 63;
        const int cc  = lin >> 6;
        const float* xp = x + ((bb * CIN + cc) * IMG) * IMG;
#pragma unroll
        for (int u = 0; u < 3; ++u) {
            const int yy = i - 1 + u;
#pragma unroll
            for (int v = 0; v < 3; ++v) {
                const int xx = j - 1 + v;
                float val = 0.f;
                if ((unsigned)yy < IMG && (unsigned)xx < IMG)
                    val = __ldg(xp + yy * IMG + xx);
                rA[idx][u * 3 + v] = val;
            }
        }
        const float* wp = w + ((size_t)(bb * CIN + cc) * POS + pos) * 9;
#pragma unroll
        for (int r = 0; r < 9; ++r) rB[idx][r] = __ldg(wp + r);
    }
#pragma unroll
    for (int idx = 0; idx < 2; ++idx) {
        const int lin = t + idx * 128;
        const int bb  = lin & 63;
        const int cc  = lin >> 6;
#pragma unroll
        for (int r = 0; r < 9; ++r) {
            sA[0][cc * 9 + r][bb] = rA[idx][r];
            sB[0][cc * 9 + r][bb] = rB[idx][r];
        }
    }
    __syncthreads();

    int buf = 0;
    for (int ch = 0; ch < NCHUNK; ++ch) {
        // prefetch next chunk into registers
        if (ch < NCHUNK - 1) {
            const int c0n = (ch + 1) * 4;
#pragma unroll
            for (int idx = 0; idx < 2; ++idx) {
                const int lin = t + idx * 128;
                const int bb  = lin & 63;
                const int cc  = lin >> 6;
                const float* xp = x + ((bb * CIN + c0n + cc) * IMG) * IMG;
#pragma unroll
                for (int u = 0; u < 3; ++u) {
                    const int yy = i - 1 + u;
#pragma unroll
                    for (int v = 0; v < 3; ++v) {
                        const int xx = j - 1 + v;
                        float val = 0.f;
                        if ((unsigned)yy < IMG && (unsigned)xx < IMG)
                            val = __ldg(xp + yy * IMG + xx);
                        rA[idx][u * 3 + v] = val;
                    }
                }
                const float* wp = w + ((size_t)(bb * CIN + c0n + cc) * POS + pos) * 9;
#pragma unroll
                for (int r = 0; r < 9; ++r) rB[idx][r] = __ldg(wp + r);
            }
        }

        // compute on current buffer
#pragma unroll
        for (int k = 0; k < KC; ++k) {
            const float4 a  = *(const float4*)&sA[buf][k][tb * 4];
            const float4 b0 = *(const float4*)&sB[buf][k][to * 8];
            const float4 b1 = *(const float4*)&sB[buf][k][to * 8 + 4];
            const float av[4] = {a.x, a.y, a.z, a.w};
            const float bv[8] = {b0.x, b0.y, b0.z, b0.w, b1.x, b1.y, b1.z, b1.w};
#pragma unroll
            for (int m = 0; m < 4; ++m)
#pragma unroll
                for (int n = 0; n < 8; ++n)
                    acc[m][n] = fmaf(av[m], bv[n], acc[m][n]);
        }

        // store prefetched regs into the other buffer
        if (ch < NCHUNK - 1) {
            const int nb = buf ^ 1;
#pragma unroll
            for (int idx = 0; idx < 2; ++idx) {
                const int lin = t + idx * 128;
                const int bb  = lin & 63;
                const int cc  = lin >> 6;
#pragma unroll
                for (int r = 0; r < 9; ++r) {
                    sA[nb][cc * 9 + r][bb] = rA[idx][r];
                    sB[nb][cc * 9 + r][bb] = rB[idx][r];
                }
            }
        }
        __syncthreads();
        buf ^= 1;
    }

    // epilogue: add bias, write transposed yt[o][pos][b] (coalesced float4)
#pragma unroll
    for (int n = 0; n < 8; ++n) {
        const int o = to * 8 + n;
        const float bs = __ldg(bias + o * POS + pos);
        const float4 v = make_float4(acc[0][n] + bs, acc[1][n] + bs,
                                     acc[2][n] + bs, acc[3][n] + bs);
        *(float4*)&g_yt[((size_t)o * POS + pos) * B_ + tb * 4] = v;
    }
}

// -------------------- Phase 2: per-channel sum / sumsq --------------------
__global__ __launch_bounds__(512)
void stats_kernel()
{
    const int o = blockIdx.x;
    const float4* p = (const float4*)(g_yt + (size_t)o * POS * B_);
    const int n4 = POS * B_ / 4;   // 16384

    float s = 0.f, ss = 0.f;
    for (int idx = threadIdx.x; idx < n4; idx += 512) {
        const float4 v = p[idx];
        s  += v.x + v.y + v.z + v.w;
        ss += v.x * v.x + v.y * v.y + v.z * v.z + v.w * v.w;
    }
#pragma unroll
    for (int off = 16; off; off >>= 1) {
        s  += __shfl_xor_sync(0xffffffffu, s,  off);
        ss += __shfl_xor_sync(0xffffffffu, ss, off);
    }
    __shared__ float shs[16], shss[16];
    const int lane = threadIdx.x & 31;
    const int wid  = threadIdx.x >> 5;
    if (lane == 0) { shs[wid] = s; shss[wid] = ss; }
    __syncthreads();
    if (threadIdx.x < 16) {
        s  = shs[threadIdx.x];
        ss = shss[threadIdx.x];
#pragma unroll
        for (int off = 8; off; off >>= 1) {
            s  += __shfl_xor_sync(0xffffu, s,  off);
            ss += __shfl_xor_sync(0xffffu, ss, off);
        }
        if (threadIdx.x == 0) { g_sum[o] = s; g_sumsq[o] = ss; }
    }
}

// ------------- Phase 3: BN normalize + ReLU + layout transpose -------------
// grid (32 i-rows, 64 channels); smem transpose so both gmem read and write
// are coalesced.
__global__ __launch_bounds__(256)
void norm_kernel(float* __restrict__ out,
                 const float* __restrict__ gamma,
                 const float* __restrict__ beta)
{
    __shared__ float tile[32][65];   // [j][b], padded
    const int i = blockIdx.x;
    const int o = blockIdx.y;
    const int t = threadIdx.x;

    for (int idx = t; idx < 32 * 64; idx += 256) {
        const int jj = idx >> 6;
        const int bb = idx & 63;
        tile[jj][bb] = g_yt[((size_t)o * POS + i * 32 + jj) * B_ + bb];
    }

    const float invN  = 1.f / (float)(POS * B_);
    const float mean  = g_sum[o] * invN;
    const float var   = g_sumsq[o] * invN - mean * mean;
    const float scale = __ldg(gamma + o) * rsqrtf(var + 1e-5f);
    const float shift = __ldg(beta + o) - mean * scale;
    __syncthreads();

    for (int idx = t; idx < 32 * 64; idx += 256) {
        const int bb = idx >> 5;
        const int jj = idx & 31;
        const float v = tile[jj][bb] * scale + shift;
        out[(((size_t)bb * COUT + o) * IMG + i) * IMG + jj] = fmaxf(v, 0.f);
    }
}

// ---------------------------------------------------------------------------
extern "C" void kernel_launch(void* const* d_in, const int* in_sizes, int n_in,
                              void* d_out, int out_size)
{
    const float* x     = (const float*)d_in[0];
    const float* w     = (const float*)d_in[1];
    const float* bias  = (const float*)d_in[2];
    const float* gamma = (const float*)d_in[3];
    const float* beta  = (const float*)d_in[4];
    float* out = (float*)d_out;

    ll_gemm_kernel<<<POS, 128>>>(x, w, bias);
    stats_kernel<<<COUT, 512>>>();
    dim3 g3(IMG, COUT);
    norm_kernel<<<g3, 256>>>(out, gamma, beta);
}

// round 2
// speedup vs baseline: 1.4650x; 1.4650x over previous
#include <cuda_runtime.h>
#include <cstdint>

#define B_      64
#define CIN     64
#define COUT    64
#define IMG     32
#define POS     1024
#define CCH     2            // channels per K-chunk
#define NCHUNK  (CIN / CCH)  // 32
#define KC      (CCH * 9)    // 18

// scratch: y (pre-BN) transposed [o][pos][b], plus per-channel stats
__device__ float g_yt[(size_t)COUT * POS * B_];
__device__ float g_sum[COUT];
__device__ float g_sumsq[COUT];

// ---------------- Phase 1: per-(row, j-quad) GEMM + bias -------------------
// block = (i, j0..j0+3): 4 independent 64b x 64o x 576k GEMMs sharing x rows.
// 256 threads: jq = t>>6 picks the j; 64 threads per j, each 8b x 8o tile.
// Weight granule per (o,c) = 4j*9uv = 36 contiguous floats, 16B aligned ->
// coalesced float4 loads (this is the whole point of the j-quad).
__global__ __launch_bounds__(256, 2)
void ll_gemm_kernel(const float* __restrict__ x,
                    const float* __restrict__ w,
                    const float* __restrict__ bias)
{
    // padded strides (68) for conflict-free scattered stores + aligned vec reads
    __shared__ float sW[4 * KC * 68];   // [jj][k=c*9+uv][o(pad 68)]
    __shared__ float sX[(CCH*3) * 8 * 68]; // [(c*3+yy)][e(8 cols)][b(pad 68)]

    const int bid = blockIdx.x;
    const int i   = bid >> 3;
    const int j0  = (bid & 7) << 2;
    const int t   = threadIdx.x;
    const int jq  = t >> 6;         // 0..3
    const int s   = t & 63;
    const int tb  = s >> 3;         // 8 b-groups of 8
    const int to  = s & 7;          // 8 o-groups of 8

    float acc[8][8];
#pragma unroll
    for (int m = 0; m < 8; ++m)
#pragma unroll
        for (int n = 0; n < 8; ++n) acc[m][n] = 0.f;

    for (int ch = 0; ch < NCHUNK; ++ch) {
        const int c0 = ch * CCH;

        // ---- load weights: 128 granules (o,c) x 9 float4 = 1152 float4 ----
        // granule g = o*CCH + c; float4 r covers flats 4r..4r+3 = jj*9+uv
        for (int f = t; f < 128 * 9; f += 256) {
            const int g = f / 9;
            const int r = f - g * 9;
            const int o = g >> 1;
            const int c = g & 1;
            const float4 v = *(const float4*)(
                w + ((size_t)(o * CIN + c0 + c) * POS + i * 32 + j0) * 9 + r * 4);
            const float vv[4] = {v.x, v.y, v.z, v.w};
#pragma unroll
            for (int l = 0; l < 4; ++l) {
                const int s4 = r * 4 + l;           // 0..35
                const int jj = s4 / 9;
                const int uv = s4 - jj * 9;
                sW[(jj * KC + c * 9 + uv) * 68 + o] = vv[l];
            }
        }

        // ---- load x: granules (c,yy,b), 8 cols j0-2..j0+5, zero-padded ----
        for (int f = t; f < 384 * 8; f += 256) {
            const int g  = f >> 3;
            const int e  = f & 7;
            const int yy = g >> 7;          // 0..2
            const int c  = (g >> 6) & 1;
            const int b  = g & 63;
            const int row = i - 1 + yy;
            const int col = j0 - 2 + e;
            float val = 0.f;
            if ((unsigned)row < IMG && (unsigned)col < IMG)
                val = __ldg(x + ((size_t)(b * CIN + c0 + c) * IMG + row) * IMG + col);
            sX[((c * 3 + yy) * 8 + e) * 68 + b] = val;
        }
        __syncthreads();

        // ---- compute: 18 k-steps, 8x8 FMA each ----
#pragma unroll
        for (int c = 0; c < CCH; ++c)
#pragma unroll
            for (int u = 0; u < 3; ++u)
#pragma unroll
                for (int v = 0; v < 3; ++v) {
                    const float* ap = &sX[((c * 3 + u) * 8 + (jq + v + 1)) * 68 + tb * 8];
                    const float4 a0 = *(const float4*)ap;
                    const float4 a1 = *(const float4*)(ap + 4);
                    const float* wp = &sW[(jq * KC + c * 9 + u * 3 + v) * 68 + to * 8];
                    const float4 w0 = *(const float4*)wp;
                    const float4 w1 = *(const float4*)(wp + 4);
                    const float av[8] = {a0.x, a0.y, a0.z, a0.w, a1.x, a1.y, a1.z, a1.w};
                    const float wv[8] = {w0.x, w0.y, w0.z, w0.w, w1.x, w1.y, w1.z, w1.w};
#pragma unroll
                    for (int m = 0; m < 8; ++m)
#pragma unroll
                        for (int n = 0; n < 8; ++n)
                            acc[m][n] = fmaf(av[m], wv[n], acc[m][n]);
                }
        __syncthreads();
    }

    // ---- epilogue: bias + transposed store yt[o][pos][b] (float4) ----
    const int pos = i * 32 + j0 + jq;
#pragma unroll
    for (int n = 0; n < 8; ++n) {
        const int o = to * 8 + n;
        const float bs = __ldg(bias + o * POS + pos);
        float* dst = &g_yt[((size_t)o * POS + pos) * B_ + tb * 8];
        *(float4*)dst =
            make_float4(acc[0][n] + bs, acc[1][n] + bs, acc[2][n] + bs, acc[3][n] + bs);
        *(float4*)(dst + 4) =
            make_float4(acc[4][n] + bs, acc[5][n] + bs, acc[6][n] + bs, acc[7][n] + bs);
    }
}

// -------------------- Phase 2: per-channel sum / sumsq --------------------
__global__ __launch_bounds__(512)
void stats_kernel()
{
    const int o = blockIdx.x;
    const float4* p = (const float4*)(g_yt + (size_t)o * POS * B_);
    const int n4 = POS * B_ / 4;

    float s = 0.f, ss = 0.f;
    for (int idx = threadIdx.x; idx < n4; idx += 512) {
        const float4 v = p[idx];
        s  += v.x + v.y + v.z + v.w;
        ss += v.x * v.x + v.y * v.y + v.z * v.z + v.w * v.w;
    }
#pragma unroll
    for (int off = 16; off; off >>= 1) {
        s  += __shfl_xor_sync(0xffffffffu, s,  off);
        ss += __shfl_xor_sync(0xffffffffu, ss, off);
    }
    __shared__ float shs[16], shss[16];
    const int lane = threadIdx.x & 31;
    const int wid  = threadIdx.x >> 5;
    if (lane == 0) { shs[wid] = s; shss[wid] = ss; }
    __syncthreads();
    if (threadIdx.x < 16) {
        s  = shs[threadIdx.x];
        ss = shss[threadIdx.x];
#pragma unroll
        for (int off = 8; off; off >>= 1) {
            s  += __shfl_xor_sync(0xffffu, s,  off);
            ss += __shfl_xor_sync(0xffffu, ss, off);
        }
        if (threadIdx.x == 0) { g_sum[o] = s; g_sumsq[o] = ss; }
    }
}

// ------------- Phase 3: BN normalize + ReLU + layout transpose -------------
__global__ __launch_bounds__(256)
void norm_kernel(float* __restrict__ out,
                 const float* __restrict__ gamma,
                 const float* __restrict__ beta)
{
    __shared__ float tile[32][65];
    const int i = blockIdx.x;
    const int o = blockIdx.y;
    const int t = threadIdx.x;

    for (int idx = t; idx < 32 * 64; idx += 256) {
        const int jj = idx >> 6;
        const int bb = idx & 63;
        tile[jj][bb] = g_yt[((size_t)o * POS + i * 32 + jj) * B_ + bb];
    }

    const float invN  = 1.f / (float)(POS * B_);
    const float mean  = g_sum[o] * invN;
    const float var   = g_sumsq[o] * invN - mean * mean;
    const float scale = __ldg(gamma + o) * rsqrtf(var + 1e-5f);
    const float shift = __ldg(beta + o) - mean * scale;
    __syncthreads();

    for (int idx = t; idx < 32 * 64; idx += 256) {
        const int bb = idx >> 5;
        const int jj = idx & 31;
        const float v = tile[jj][bb] * scale + shift;
        out[(((size_t)bb * COUT + o) * IMG + i) * IMG + jj] = fmaxf(v, 0.f);
    }
}

// ---------------------------------------------------------------------------
extern "C" void kernel_launch(void* const* d_in, const int* in_sizes, int n_in,
                              void* d_out, int out_size)
{
    const float* x     = (const float*)d_in[0];
    const float* w     = (const float*)d_in[1];
    const float* bias  = (const float*)d_in[2];
    const float* gamma = (const float*)d_in[3];
    const float* beta  = (const float*)d_in[4];
    float* out = (float*)d_out;

    ll_gemm_kernel<<<256, 256>>>(x, w, bias);
    stats_kernel<<<COUT, 512>>>();
    dim3 g3(IMG, COUT);
    norm_kernel<<<g3, 256>>>(out, gamma, beta);
}

// round 4
// speedup vs baseline: 1.8694x; 1.2761x over previous
#include <cuda_runtime.h>
#include <cstdint>

#define B_      64
#define CIN     64
#define COUT    64
#define IMG     32
#define POS     1024
#define CCH     4              // channels per chunk
#define NCH     (CIN / CCH)    // 16 chunks
#define KCHK    36             // real k per chunk
#define KPAD    40             // padded to 5 k8-steps
#define KST     44             // smem k-stride (44%32=12 -> conflict-free frags)
#define TILEF   (64 * KST)     // floats per (jj) tile
#define SMEM_BYTES (2 * 4 * TILEF * 4)   // sA + sB = 90112

__device__ float g_yt[(size_t)COUT * POS * B_];
__device__ float g_sum[COUT];
__device__ float g_sumsq[COUT];

__device__ __forceinline__ uint32_t to_tf32(float f) {
    uint32_t r;
    asm("cvt.rna.tf32.f32 %0, %1;" : "=r"(r) : "f"(f));
    return r;
}
__device__ __forceinline__ void mma8(float* c, const uint32_t* a,
                                     uint32_t b0, uint32_t b1) {
    asm volatile(
        "mma.sync.aligned.m16n8k8.row.col.f32.tf32.tf32.f32 "
        "{%0,%1,%2,%3}, {%4,%5,%6,%7}, {%8,%9}, {%0,%1,%2,%3};"
        : "+f"(c[0]), "+f"(c[1]), "+f"(c[2]), "+f"(c[3])
        : "r"(a[0]), "r"(a[1]), "r"(a[2]), "r"(a[3]), "r"(b0), "r"(b1));
}

// ---------------- Phase 1: tf32 mma.sync GEMM ----------------
// block = (i, j0..j0+3); warp w: jj=w>>1, half=w&1 -> 32(b) x 64(o) C tile.
__global__ __launch_bounds__(256, 2)
void ll_mma_kernel(const float* __restrict__ x,
                   const float* __restrict__ w,
                   const float* __restrict__ bias)
{
    extern __shared__ uint32_t smem[];
    uint32_t* sA = smem;                 // [jj][b][KST]
    uint32_t* sB = smem + 4 * TILEF;     // [jj][o][KST]

    const int bid  = blockIdx.x;
    const int i    = bid >> 3;
    const int j0   = (bid & 7) << 2;
    const int posb = i * 32 + j0;
    const int t    = threadIdx.x;
    const int lane = t & 31;
    const int warp = t >> 5;
    const int jj   = warp >> 1;
    const int half = warp & 1;
    const int grp  = lane >> 2;      // 0..7
    const int tig  = lane & 3;       // 0..3

    float acc[2][8][4];
#pragma unroll
    for (int mt = 0; mt < 2; ++mt)
#pragma unroll
        for (int nt = 0; nt < 8; ++nt)
#pragma unroll
            for (int q = 0; q < 4; ++q) acc[mt][nt][q] = 0.f;

    // zero the k-pad columns (36..39) once
    for (int idx = t; idx < 4 * 64 * 4; idx += 256) {
        const int tj = idx >> 8;
        const int r  = (idx >> 2) & 63;
        const int q  = idx & 3;
        sA[tj * TILEF + r * KST + KCHK + q] = 0u;
        sB[tj * TILEF + r * KST + KCHK + q] = 0u;
    }

    for (int ch = 0; ch < NCH; ++ch) {
        const int c0 = ch * CCH;

        // ---- weights: 256 granules (o,cl) x 9 float4, coalesced LDG.128 ----
        for (int f = t; f < 256 * 9; f += 256) {
            const int go = f / 9;
            const int r  = f - go * 9;
            const int o  = go >> 2, cl = go & 3;
            const float4 v = *(const float4*)(
                w + ((size_t)(o * CIN + c0 + cl) * POS + posb) * 9 + r * 4);
            const float vv[4] = {v.x, v.y, v.z, v.w};
#pragma unroll
            for (int l = 0; l < 4; ++l) {
                const int s4 = r * 4 + l;          // 0..35 = jj*9 + uv
                const int tj = s4 / 9;
                const int uv = s4 - tj * 9;
                sB[tj * TILEF + o * KST + cl * 9 + uv] = to_tf32(vv[l]);
            }
        }
        // ---- x: (cl,u,b,e) grid, scatter to all (jj, v) with jj+v == e ----
        for (int f = t; f < CCH * 3 * 64 * 6; f += 256) {
            const int e   = f % 6;
            const int b   = (f / 6) & 63;
            const int u   = (f / 384) % 3;
            const int cl  = f / 1152;
            const int row = i - 1 + u;
            const int col = j0 - 1 + e;
            float val = 0.f;
            if ((unsigned)row < IMG && (unsigned)col < IMG)
                val = __ldg(x + ((size_t)(b * CIN + c0 + cl) * IMG + row) * IMG + col);
            const uint32_t tv = to_tf32(val);
#pragma unroll
            for (int v = 0; v < 3; ++v) {
                const int tj = e - v;
                if (0 <= tj && tj <= 3)
                    sA[tj * TILEF + b * KST + cl * 9 + u * 3 + v] = tv;
            }
        }
        __syncthreads();

        // ---- compute: 5 k8-steps, 2x8 m16n8 tiles ----
        const uint32_t* Aj = sA + jj * TILEF;
        const uint32_t* Bj = sB + jj * TILEF;
#pragma unroll
        for (int ks = 0; ks < 5; ++ks) {
            const int kc0 = ks * 8 + tig;
            uint32_t a[2][4];
#pragma unroll
            for (int mt = 0; mt < 2; ++mt) {
                const uint32_t* ap = Aj + (half * 32 + mt * 16 + grp) * KST + kc0;
                a[mt][0] = ap[0];
                a[mt][1] = ap[8 * KST];
                a[mt][2] = ap[4];
                a[mt][3] = ap[8 * KST + 4];
            }
#pragma unroll
            for (int nt = 0; nt < 8; ++nt) {
                const uint32_t* bp = Bj + (nt * 8 + grp) * KST + kc0;
                const uint32_t b0 = bp[0];
                const uint32_t b1 = bp[4];
                mma8(acc[0][nt], a[0], b0, b1);
                mma8(acc[1][nt], a[1], b0, b1);
            }
        }
        __syncthreads();
    }

    // ---- epilogue: bias + store to yt[o][pos][b] ----
    const int pos = posb + jj;
#pragma unroll
    for (int nt = 0; nt < 8; ++nt) {
        const int o0 = nt * 8 + tig * 2;
        const float bs0 = __ldg(bias + o0 * POS + pos);
        const float bs1 = __ldg(bias + (o0 + 1) * POS + pos);
#pragma unroll
        for (int mt = 0; mt < 2; ++mt) {
            const int b = half * 32 + mt * 16 + grp;
            float* y0 = &g_yt[((size_t)o0 * POS + pos) * B_ + b];
            float* y1 = &g_yt[((size_t)(o0 + 1) * POS + pos) * B_ + b];
            y0[0] = acc[mt][nt][0] + bs0;
            y1[0] = acc[mt][nt][1] + bs1;
            y0[8] = acc[mt][nt][2] + bs0;
            y1[8] = acc[mt][nt][3] + bs1;
        }
    }
}

// -------------------- Phase 2: per-channel sum / sumsq --------------------
__global__ __launch_bounds__(512)
void stats_kernel()
{
    const int o = blockIdx.x;
    const float4* p = (const float4*)(g_yt + (size_t)o * POS * B_);
    const int n4 = POS * B_ / 4;

    float s = 0.f, ss = 0.f;
    for (int idx = threadIdx.x; idx < n4; idx += 512) {
        const float4 v = p[idx];
        s  += v.x + v.y + v.z + v.w;
        ss += v.x * v.x + v.y * v.y + v.z * v.z + v.w * v.w;
    }
#pragma unroll
    for (int off = 16; off; off >>= 1) {
        s  += __shfl_xor_sync(0xffffffffu, s,  off);
        ss += __shfl_xor_sync(0xffffffffu, ss, off);
    }
    __shared__ float shs[16], shss[16];
    const int lane = threadIdx.x & 31;
    const int wdx  = threadIdx.x >> 5;
    if (lane == 0) { shs[wdx] = s; shss[wdx] = ss; }
    __syncthreads();
    if (threadIdx.x < 16) {
        s  = shs[threadIdx.x];
        ss = shss[threadIdx.x];
#pragma unroll
        for (int off = 8; off; off >>= 1) {
            s  += __shfl_xor_sync(0xffffu, s,  off);
            ss += __shfl_xor_sync(0xffffu, ss, off);
        }
        if (threadIdx.x == 0) { g_sum[o] = s; g_sumsq[o] = ss; }
    }
}

// ------------- Phase 3: BN normalize + ReLU + layout transpose -------------
__global__ __launch_bounds__(256)
void norm_kernel(float* __restrict__ out,
                 const float* __restrict__ gamma,
                 const float* __restrict__ beta)
{
    __shared__ float tile[32][65];
    const int i = blockIdx.x;
    const int o = blockIdx.y;
    const int t = threadIdx.x;

    for (int idx = t; idx < 32 * 64; idx += 256) {
        const int jj = idx >> 6;
        const int bb = idx & 63;
        tile[jj][bb] = g_yt[((size_t)o * POS + i * 32 + jj) * B_ + bb];
    }

    const float invN  = 1.f / (float)(POS * B_);
    const float mean  = g_sum[o] * invN;
    const float var   = g_sumsq[o] * invN - mean * mean;
    const float scale = __ldg(gamma + o) * rsqrtf(var + 1e-5f);
    const float shift = __ldg(beta + o) - mean * scale;
    __syncthreads();

    for (int idx = t; idx < 32 * 64; idx += 256) {
        const int bb = idx >> 5;
        const int jj = idx & 31;
        const float v = tile[jj][bb] * scale + shift;
        out[(((size_t)bb * COUT + o) * IMG + i) * IMG + jj] = fmaxf(v, 0.f);
    }
}

// ---------------------------------------------------------------------------
extern "C" void kernel_launch(void* const* d_in, const int* in_sizes, int n_in,
                              void* d_out, int out_size)
{
    const float* x     = (const float*)d_in[0];
    const float* w     = (const float*)d_in[1];
    const float* bias  = (const float*)d_in[2];
    const float* gamma = (const float*)d_in[3];
    const float* beta  = (const float*)d_in[4];
    float* out = (float*)d_out;

    cudaFuncSetAttribute(ll_mma_kernel,
                         cudaFuncAttributeMaxDynamicSharedMemorySize, SMEM_BYTES);
    ll_mma_kernel<<<256, 256, SMEM_BYTES>>>(x, w, bias);
    stats_kernel<<<COUT, 512>>>();
    dim3 g3(IMG, COUT);
    norm_kernel<<<g3, 256>>>(out, gamma, beta);
}

// round 6
// speedup vs baseline: 3.7804x; 2.0222x over previous
#include <cuda_runtime.h>
#include <cstdint>

#define B_      64
#define CIN     64
#define COUT    64
#define IMG     32
#define POS     1024
#define CCH     2                 // channels per chunk
#define NCH     32                // 64 / 2
#define WSTRIDE 76                // floats per o-row in W stage (2*36 + 4 pad)
#define WBUF_F  (64 * WSTRIDE)    // 4864 floats
#define XSTRIDE 12                // floats per (g,b) row in X stage (8 used)
#define XBUF_F  (6 * 64 * XSTRIDE) // 4608 floats
#define SMEM_F  (2 * WBUF_F + 2 * XBUF_F)   // 18944 floats
#define SMEM_BYTES (SMEM_F * 4)             // 75776

__device__ float g_yt[(size_t)COUT * POS * B_];
__device__ float g_partS[COUT * 256];
__device__ float g_partQ[COUT * 256];
__device__ float g_sum[COUT];
__device__ float g_sumsq[COUT];

__device__ __forceinline__ uint32_t to_tf32(float f) {
    uint32_t r;
    asm("cvt.rna.tf32.f32 %0, %1;" : "=r"(r) : "f"(f));
    return r;
}
__device__ __forceinline__ void mma8(float* c, const uint32_t* a,
                                     uint32_t b0, uint32_t b1) {
    asm volatile(
        "mma.sync.aligned.m16n8k8.row.col.f32.tf32.tf32.f32 "
        "{%0,%1,%2,%3}, {%4,%5,%6,%7}, {%8,%9}, {%0,%1,%2,%3};"
        : "+f"(c[0]), "+f"(c[1]), "+f"(c[2]), "+f"(c[3])
        : "r"(a[0]), "r"(a[1]), "r"(a[2]), "r"(a[3]), "r"(b0), "r"(b1));
}
__device__ __forceinline__ uint32_t sptr(const void* p) {
    uint32_t a;
    asm("{ .reg .u64 t; cvta.to.shared.u64 t, %1; cvt.u32.u64 %0, t; }" : "=r"(a) : "l"(p));
    return a;
}
__device__ __forceinline__ void cp16(uint32_t dst, const void* src) {
    asm volatile("cp.async.cg.shared.global [%0], [%1], 16;"
                 :: "r"(dst), "l"(src) : "memory");
}
#define CP_COMMIT() asm volatile("cp.async.commit_group;" ::: "memory")
#define CP_WAIT(N)  asm volatile("cp.async.wait_group %0;" :: "n"(N) : "memory")

// issue cp.async for one chunk of weights (128 granules x 9 float4)
__device__ __forceinline__ void stage_w(const float* __restrict__ w,
                                        int c0, int posb, int t, uint32_t wdst)
{
    for (int f = t; f < 1152; f += 256) {
        const int go = f / 9;
        const int r  = f - go * 9;
        const int o  = go >> 1, cl = go & 1;
        const float* src = w + ((size_t)(o * CIN + c0 + cl) * POS + posb) * 9 + r * 4;
        cp16(wdst + (uint32_t)((o * WSTRIDE + cl * 36 + r * 4) * 4), src);
    }
    CP_COMMIT();
}

// guarded x loads for one chunk into registers (6 float2 / thread)
__device__ __forceinline__ void load_x(const float* __restrict__ x,
                                       int c0, int i, int j0, int t, float2* rx)
{
#pragma unroll
    for (int l = 0; l < 6; ++l) {
        const int f     = t + l * 256;
        const int q     = f & 3;
        const int rowid = f >> 2;
        const int b     = rowid & 63;
        const int g     = rowid >> 6;      // cl*3+u
        const int cl    = (g >= 3);
        const int u     = g - cl * 3;
        const int row   = i - 1 + u;
        const int col   = j0 - 2 + 2 * q;
        float2 v = make_float2(0.f, 0.f);
        const bool ok = ((unsigned)row < IMG) &&
                        !(q == 0 && j0 == 0) && !(q == 3 && j0 == 28);
        if (ok)
            v = *(const float2*)(x + ((size_t)(b * CIN + c0 + cl) * IMG + row) * IMG + col);
        rx[l] = v;
    }
}

// unconditional STS of prefetched x registers (halos become explicit zeros)
__device__ __forceinline__ void store_x(float* xbuf, int t, const float2* rx)
{
#pragma unroll
    for (int l = 0; l < 6; ++l) {
        const int f     = t + l * 256;
        const int q     = f & 3;
        const int rowid = f >> 2;
        *(float2*)(xbuf + rowid * XSTRIDE + 2 * q) = rx[l];
    }
}

// ---------------- Phase 1: pipelined tf32 mma.sync GEMM ----------------
__global__ __launch_bounds__(256, 2)
void ll_mma_kernel(const float* __restrict__ x,
                   const float* __restrict__ w,
                   const float* __restrict__ bias)
{
    extern __shared__ float smem[];
    const uint32_t sbase = sptr(smem);

    const int bid  = blockIdx.x;
    const int i    = bid >> 3;
    const int j0   = (bid & 7) << 2;
    const int posb = i * 32 + j0;
    const int t    = threadIdx.x;
    const int lane = t & 31;
    const int warp = t >> 5;
    const int jj   = warp >> 1;
    const int half = warp & 1;
    const int grp  = lane >> 2;
    const int tig  = lane & 3;

    float acc[2][8][4];
#pragma unroll
    for (int mt = 0; mt < 2; ++mt)
#pragma unroll
        for (int nt = 0; nt < 8; ++nt)
#pragma unroll
            for (int q = 0; q < 4; ++q) acc[mt][nt][q] = 0.f;

    // prologue: x(0) via regs -> buf0, W(0) via cp.async -> buf0
    {
        float2 rx[6];
        load_x(x, 0, i, j0, t, rx);
        store_x(smem + 2 * WBUF_F, t, rx);
        stage_w(w, 0, posb, t, sbase);
    }

    for (int ch = 0; ch < NCH; ++ch) {
        const int buf = ch & 1;
        const int nb  = buf ^ 1;
        float2 rx[6];
        if (ch + 1 < NCH) {
            load_x(x, (ch + 1) * CCH, i, j0, t, rx);                 // prefetch x
            stage_w(w, (ch + 1) * CCH, posb, t,
                    sbase + (uint32_t)(nb * WBUF_F * 4));            // prefetch W
            CP_WAIT(1);
        } else {
            CP_WAIT(0);
        }
        __syncthreads();   // buf's W (cp.async) and X (prev STS) now visible

        const float* Wb = smem + buf * WBUF_F;
        const float* Xb = smem + 2 * WBUF_F + buf * XBUF_F;

#pragma unroll
        for (int ks = 0; ks < 3; ++ks) {
            const int  k1 = ks * 8 + tig;
            const bool v1 = (ks < 2) || (tig < 2);
            const int cl1 = (k1 >= 9) ? 1 : 0;
            const int r1  = k1 - cl1 * 9;
            const int u1  = r1 / 3;
            const int vv1 = r1 - u1 * 3;
            const int xo1 = (cl1 * 3 + u1) * 768 + jj + vv1 + 1;
            const int wo1 = cl1 * 36 + jj * 9 + r1;
            int xo2 = 0, wo2 = 0;
            if (ks < 2) {
                const int k2  = k1 + 4;
                const int cl2 = (k2 >= 9) ? 1 : 0;
                const int r2  = k2 - cl2 * 9;
                const int u2  = r2 / 3;
                const int vv2 = r2 - u2 * 3;
                xo2 = (cl2 * 3 + u2) * 768 + jj + vv2 + 1;
                wo2 = cl2 * 36 + jj * 9 + r2;
            }
            uint32_t a[2][4];
#pragma unroll
            for (int mt = 0; mt < 2; ++mt) {
                const int br = half * 32 + mt * 16 + grp;
                const float f0 = v1 ? Xb[xo1 + br * XSTRIDE] : 0.f;
                const float f1 = v1 ? Xb[xo1 + (br + 8) * XSTRIDE] : 0.f;
                const float f2 = (ks < 2) ? Xb[xo2 + br * XSTRIDE] : 0.f;
                const float f3 = (ks < 2) ? Xb[xo2 + (br + 8) * XSTRIDE] : 0.f;
                a[mt][0] = to_tf32(f0); a[mt][1] = to_tf32(f1);
                a[mt][2] = to_tf32(f2); a[mt][3] = to_tf32(f3);
            }
#pragma unroll
            for (int nt = 0; nt < 8; ++nt) {
                const int o = nt * 8 + grp;
                const float bf0 = v1 ? Wb[o * WSTRIDE + wo1] : 0.f;
                const float bf1 = (ks < 2) ? Wb[o * WSTRIDE + wo2] : 0.f;
                const uint32_t b0 = to_tf32(bf0);
                const uint32_t b1 = to_tf32(bf1);
                mma8(acc[0][nt], a[0], b0, b1);
                mma8(acc[1][nt], a[1], b0, b1);
            }
        }
        __syncthreads();   // all reads of buf done before next-iter staging reuses it

        if (ch + 1 < NCH)
            store_x(smem + 2 * WBUF_F + nb * XBUF_F, t, rx);  // X(ch+1) -> nb
    }

    // ---- epilogue: bias + store yt + fused per-block BN partials ----
    const int pos = posb + jj;
    float* redS = smem;          // reuse buf0 W stage (no pending async writes)
    float* redQ = smem + 512;

#pragma unroll
    for (int nt = 0; nt < 8; ++nt) {
        const int o0 = nt * 8 + tig * 2;
        const float bs0 = __ldg(bias + o0 * POS + pos);
        const float bs1 = __ldg(bias + (o0 + 1) * POS + pos);
        float y[2][4];
#pragma unroll
        for (int mt = 0; mt < 2; ++mt) {
            y[mt][0] = acc[mt][nt][0] + bs0;
            y[mt][1] = acc[mt][nt][1] + bs1;
            y[mt][2] = acc[mt][nt][2] + bs0;
            y[mt][3] = acc[mt][nt][3] + bs1;
            const int b = half * 32 + mt * 16 + grp;
            g_yt[((size_t)o0 * POS + pos) * B_ + b]           = y[mt][0];
            g_yt[((size_t)(o0 + 1) * POS + pos) * B_ + b]     = y[mt][1];
            g_yt[((size_t)o0 * POS + pos) * B_ + b + 8]       = y[mt][2];
            g_yt[((size_t)(o0 + 1) * POS + pos) * B_ + b + 8] = y[mt][3];
        }
        float se = y[0][0] + y[0][2] + y[1][0] + y[1][2];
        float so = y[0][1] + y[0][3] + y[1][1] + y[1][3];
        float qe = y[0][0]*y[0][0] + y[0][2]*y[0][2] + y[1][0]*y[1][0] + y[1][2]*y[1][2];
        float qo = y[0][1]*y[0][1] + y[0][3]*y[0][3] + y[1][1]*y[1][1] + y[1][3]*y[1][3];
#pragma unroll
        for (int off = 4; off <= 16; off <<= 1) {
            se += __shfl_xor_sync(0xffffffffu, se, off);
            so += __shfl_xor_sync(0xffffffffu, so, off);
            qe += __shfl_xor_sync(0xffffffffu, qe, off);
            qo += __shfl_xor_sync(0xffffffffu, qo, off);
        }
        if (grp == 0) {
            redS[warp * 64 + o0]     = se;
            redS[warp * 64 + o0 + 1] = so;
            redQ[warp * 64 + o0]     = qe;
            redQ[warp * 64 + o0 + 1] = qo;
        }
    }
    __syncthreads();
    if (t < 64) {
        float S = 0.f, Q = 0.f;
#pragma unroll
        for (int ww = 0; ww < 8; ++ww) { S += redS[ww * 64 + t]; Q += redQ[ww * 64 + t]; }
        g_partS[t * 256 + bid] = S;
        g_partQ[t * 256 + bid] = Q;
    }
}

// -------------------- Phase 2: tiny partial reduce --------------------
__global__ __launch_bounds__(256)
void stats2_kernel()
{
    const int o = blockIdx.x;
    const int t = threadIdx.x;
    float s = g_partS[o * 256 + t];
    float q = g_partQ[o * 256 + t];
#pragma unroll
    for (int off = 16; off; off >>= 1) {
        s += __shfl_xor_sync(0xffffffffu, s, off);
        q += __shfl_xor_sync(0xffffffffu, q, off);
    }
    __shared__ float shs[8], shq[8];
    if ((t & 31) == 0) { shs[t >> 5] = s; shq[t >> 5] = q; }
    __syncthreads();
    if (t < 8) {
        s = shs[t]; q = shq[t];
#pragma unroll
        for (int off = 4; off; off >>= 1) {
            s += __shfl_xor_sync(0xffu, s, off);
            q += __shfl_xor_sync(0xffu, q, off);
        }
        if (t == 0) { g_sum[o] = s; g_sumsq[o] = q; }
    }
}

// ------------- Phase 3: BN normalize + ReLU + layout transpose -------------
__global__ __launch_bounds__(256)
void norm_kernel(float* __restrict__ out,
                 const float* __restrict__ gamma,
                 const float* __restrict__ beta)
{
    __shared__ float tile[32][65];
    const int i = blockIdx.x;
    const int o = blockIdx.y;
    const int t = threadIdx.x;

    for (int idx = t; idx < 32 * 64; idx += 256) {
        const int jj = idx >> 6;
        const int bb = idx & 63;
        tile[jj][bb] = g_yt[((size_t)o * POS + i * 32 + jj) * B_ + bb];
    }

    const float invN  = 1.f / (float)(POS * B_);
    const float mean  = g_sum[o] * invN;
    const float var   = g_sumsq[o] * invN - mean * mean;
    const float scale = __ldg(gamma + o) * rsqrtf(var + 1e-5f);
    const float shift = __ldg(beta + o) - mean * scale;
    __syncthreads();

    for (int idx = t; idx < 32 * 64; idx += 256) {
        const int bb = idx >> 5;
        const int jj = idx & 31;
        const float v = tile[jj][bb] * scale + shift;
        out[(((size_t)bb * COUT + o) * IMG + i) * IMG + jj] = fmaxf(v, 0.f);
    }
}

// ---------------------------------------------------------------------------
extern "C" void kernel_launch(void* const* d_in, const int* in_sizes, int n_in,
                              void* d_out, int out_size)
{
    const float* x     = (const float*)d_in[0];
    const float* w     = (const float*)d_in[1];
    const float* bias  = (const float*)d_in[2];
    const float* gamma = (const float*)d_in[3];
    const float* beta  = (const float*)d_in[4];
    float* out = (float*)d_out;

    cudaFuncSetAttribute(ll_mma_kernel,
                         cudaFuncAttributeMaxDynamicSharedMemorySize, SMEM_BYTES);
    ll_mma_kernel<<<256, 256, SMEM_BYTES>>>(x, w, bias);
    stats2_kernel<<<COUT, 256>>>();
    dim3 g3(IMG, COUT);
    norm_kernel<<<g3, 256>>>(out, gamma, beta);
}

// round 7
// speedup vs baseline: 3.8444x; 1.0169x over previous
#include <cuda_runtime.h>
#include <cstdint>

#define B_      64
#define CIN     64
#define COUT    64
#define IMG     32
#define POS     1024
#define CCH     2                 // channels per chunk
#define NCH     32                // 64 / 2
#define WSTRIDE 76                // floats per o-row in W stage (2*36 + 4 pad)
#define WBUF_F  (64 * WSTRIDE)    // 4864 floats
#define XSTRIDE 12                // floats per (g,b) row in X stage (8 used)
#define XBUF_F  (6 * 64 * XSTRIDE) // 4608 floats
#define SMEM_F  (2 * WBUF_F + 2 * XBUF_F)   // 18944 floats
#define SMEM_BYTES (SMEM_F * 4)             // 75776

__device__ float g_yt[(size_t)COUT * POS * B_];
__device__ float g_partS[COUT * 256];
__device__ float g_partQ[COUT * 256];
__device__ float g_sum[COUT];
__device__ float g_sumsq[COUT];

__device__ __forceinline__ uint32_t to_tf32(float f) {
    uint32_t r;
    asm("cvt.rna.tf32.f32 %0, %1;" : "=r"(r) : "f"(f));
    return r;
}
__device__ __forceinline__ void mma8(float* c, const uint32_t* a,
                                     uint32_t b0, uint32_t b1) {
    asm volatile(
        "mma.sync.aligned.m16n8k8.row.col.f32.tf32.tf32.f32 "
        "{%0,%1,%2,%3}, {%4,%5,%6,%7}, {%8,%9}, {%0,%1,%2,%3};"
        : "+f"(c[0]), "+f"(c[1]), "+f"(c[2]), "+f"(c[3])
        : "r"(a[0]), "r"(a[1]), "r"(a[2]), "r"(a[3]), "r"(b0), "r"(b1));
}
__device__ __forceinline__ uint32_t sptr(const void* p) {
    uint32_t a;
    asm("{ .reg .u64 t; cvta.to.shared.u64 t, %1; cvt.u32.u64 %0, t; }" : "=r"(a) : "l"(p));
    return a;
}
__device__ __forceinline__ void cp16(uint32_t dst, const void* src) {
    asm volatile("cp.async.cg.shared.global [%0], [%1], 16;"
                 :: "r"(dst), "l"(src) : "memory");
}
#define CP_COMMIT() asm volatile("cp.async.commit_group;" ::: "memory")
#define CP_WAIT(N)  asm volatile("cp.async.wait_group %0;" :: "n"(N) : "memory")

// issue cp.async for one chunk of weights (128 granules x 9 float4)
__device__ __forceinline__ void stage_w(const float* __restrict__ w,
                                        int c0, int posb, int t, uint32_t wdst)
{
    for (int f = t; f < 1152; f += 256) {
        const int go = f / 9;
        const int r  = f - go * 9;
        const int o  = go >> 1, cl = go & 1;
        const float* src = w + ((size_t)(o * CIN + c0 + cl) * POS + posb) * 9 + r * 4;
        cp16(wdst + (uint32_t)((o * WSTRIDE + cl * 36 + r * 4) * 4), src);
    }
    CP_COMMIT();
}

// guarded x loads for one chunk into registers (6 float2 / thread)
__device__ __forceinline__ void load_x(const float* __restrict__ x,
                                       int c0, int i, int j0, int t, float2* rx)
{
#pragma unroll
    for (int l = 0; l < 6; ++l) {
        const int f     = t + l * 256;
        const int q     = f & 3;
        const int rowid = f >> 2;
        const int b     = rowid & 63;
        const int g     = rowid >> 6;      // cl*3+u
        const int cl    = (g >= 3);
        const int u     = g - cl * 3;
        const int row   = i - 1 + u;
        const int col   = j0 - 2 + 2 * q;
        float2 v = make_float2(0.f, 0.f);
        const bool ok = ((unsigned)row < IMG) &&
                        !(q == 0 && j0 == 0) && !(q == 3 && j0 == 28);
        if (ok)
            v = *(const float2*)(x + ((size_t)(b * CIN + c0 + cl) * IMG + row) * IMG + col);
        rx[l] = v;
    }
}

// unconditional STS of prefetched x registers (halos become explicit zeros)
__device__ __forceinline__ void store_x(float* xbuf, int t, const float2* rx)
{
#pragma unroll
    for (int l = 0; l < 6; ++l) {
        const int f     = t + l * 256;
        const int q     = f & 3;
        const int rowid = f >> 2;
        *(float2*)(xbuf + rowid * XSTRIDE + 2 * q) = rx[l];
    }
}

// ---------------- Phase 1: pipelined tf32 mma.sync GEMM ----------------
__global__ __launch_bounds__(256, 2)
void ll_mma_kernel(const float* __restrict__ x,
                   const float* __restrict__ w,
                   const float* __restrict__ bias)
{
    extern __shared__ float smem[];
    const uint32_t sbase = sptr(smem);

    const int bid  = blockIdx.x;
    const int i    = bid >> 3;
    const int j0   = (bid & 7) << 2;
    const int posb = i * 32 + j0;
    const int t    = threadIdx.x;
    const int lane = t & 31;
    const int warp = t >> 5;
    const int jj   = warp >> 1;
    const int half = warp & 1;
    const int grp  = lane >> 2;
    const int tig  = lane & 3;

    float acc[2][8][4];
#pragma unroll
    for (int mt = 0; mt < 2; ++mt)
#pragma unroll
        for (int nt = 0; nt < 8; ++nt)
#pragma unroll
            for (int q = 0; q < 4; ++q) acc[mt][nt][q] = 0.f;

    // prologue: x(0) via regs -> buf0, W(0) via cp.async -> buf0
    {
        float2 rx[6];
        load_x(x, 0, i, j0, t, rx);
        store_x(smem + 2 * WBUF_F, t, rx);
        stage_w(w, 0, posb, t, sbase);
    }

    for (int ch = 0; ch < NCH; ++ch) {
        const int buf = ch & 1;
        const int nb  = buf ^ 1;
        float2 rx[6];
        if (ch + 1 < NCH) {
            load_x(x, (ch + 1) * CCH, i, j0, t, rx);                 // prefetch x
            stage_w(w, (ch + 1) * CCH, posb, t,
                    sbase + (uint32_t)(nb * WBUF_F * 4));            // prefetch W
            CP_WAIT(1);
        } else {
            CP_WAIT(0);
        }
        __syncthreads();   // buf's W (cp.async) and X (prev STS) now visible

        const float* Wb = smem + buf * WBUF_F;
        const float* Xb = smem + 2 * WBUF_F + buf * XBUF_F;

#pragma unroll
        for (int ks = 0; ks < 3; ++ks) {
            const int  k1 = ks * 8 + tig;
            const bool v1 = (ks < 2) || (tig < 2);
            const int cl1 = (k1 >= 9) ? 1 : 0;
            const int r1  = k1 - cl1 * 9;
            const int u1  = r1 / 3;
            const int vv1 = r1 - u1 * 3;
            const int xo1 = (cl1 * 3 + u1) * 768 + jj + vv1 + 1;
            const int wo1 = cl1 * 36 + jj * 9 + r1;
            int xo2 = 0, wo2 = 0;
            if (ks < 2) {
                const int k2  = k1 + 4;
                const int cl2 = (k2 >= 9) ? 1 : 0;
                const int r2  = k2 - cl2 * 9;
                const int u2  = r2 / 3;
                const int vv2 = r2 - u2 * 3;
                xo2 = (cl2 * 3 + u2) * 768 + jj + vv2 + 1;
                wo2 = cl2 * 36 + jj * 9 + r2;
            }
            uint32_t a[2][4];
#pragma unroll
            for (int mt = 0; mt < 2; ++mt) {
                const int br = half * 32 + mt * 16 + grp;
                const float f0 = v1 ? Xb[xo1 + br * XSTRIDE] : 0.f;
                const float f1 = v1 ? Xb[xo1 + (br + 8) * XSTRIDE] : 0.f;
                const float f2 = (ks < 2) ? Xb[xo2 + br * XSTRIDE] : 0.f;
                const float f3 = (ks < 2) ? Xb[xo2 + (br + 8) * XSTRIDE] : 0.f;
                a[mt][0] = to_tf32(f0); a[mt][1] = to_tf32(f1);
                a[mt][2] = to_tf32(f2); a[mt][3] = to_tf32(f3);
            }
#pragma unroll
            for (int nt = 0; nt < 8; ++nt) {
                const int o = nt * 8 + grp;
                const float bf0 = v1 ? Wb[o * WSTRIDE + wo1] : 0.f;
                const float bf1 = (ks < 2) ? Wb[o * WSTRIDE + wo2] : 0.f;
                const uint32_t b0 = to_tf32(bf0);
                const uint32_t b1 = to_tf32(bf1);
                mma8(acc[0][nt], a[0], b0, b1);
                mma8(acc[1][nt], a[1], b0, b1);
            }
        }
        __syncthreads();   // all reads of buf done before next-iter staging reuses it

        if (ch + 1 < NCH)
            store_x(smem + 2 * WBUF_F + nb * XBUF_F, t, rx);  // X(ch+1) -> nb
    }

    // ---- epilogue: bias + store yt + fused per-block BN partials ----
    const int pos = posb + jj;
    float* redS = smem;          // reuse buf0 W stage (no pending async writes)
    float* redQ = smem + 512;

#pragma unroll
    for (int nt = 0; nt < 8; ++nt) {
        const int o0 = nt * 8 + tig * 2;
        const float bs0 = __ldg(bias + o0 * POS + pos);
        const float bs1 = __ldg(bias + (o0 + 1) * POS + pos);
        float y[2][4];
#pragma unroll
        for (int mt = 0; mt < 2; ++mt) {
            y[mt][0] = acc[mt][nt][0] + bs0;
            y[mt][1] = acc[mt][nt][1] + bs1;
            y[mt][2] = acc[mt][nt][2] + bs0;
            y[mt][3] = acc[mt][nt][3] + bs1;
            const int b = half * 32 + mt * 16 + grp;
            g_yt[((size_t)o0 * POS + pos) * B_ + b]           = y[mt][0];
            g_yt[((size_t)(o0 + 1) * POS + pos) * B_ + b]     = y[mt][1];
            g_yt[((size_t)o0 * POS + pos) * B_ + b + 8]       = y[mt][2];
            g_yt[((size_t)(o0 + 1) * POS + pos) * B_ + b + 8] = y[mt][3];
        }
        float se = y[0][0] + y[0][2] + y[1][0] + y[1][2];
        float so = y[0][1] + y[0][3] + y[1][1] + y[1][3];
        float qe = y[0][0]*y[0][0] + y[0][2]*y[0][2] + y[1][0]*y[1][0] + y[1][2]*y[1][2];
        float qo = y[0][1]*y[0][1] + y[0][3]*y[0][3] + y[1][1]*y[1][1] + y[1][3]*y[1][3];
#pragma unroll
        for (int off = 4; off <= 16; off <<= 1) {
            se += __shfl_xor_sync(0xffffffffu, se, off);
            so += __shfl_xor_sync(0xffffffffu, so, off);
            qe += __shfl_xor_sync(0xffffffffu, qe, off);
            qo += __shfl_xor_sync(0xffffffffu, qo, off);
        }
        if (grp == 0) {
            redS[warp * 64 + o0]     = se;
            redS[warp * 64 + o0 + 1] = so;
            redQ[warp * 64 + o0]     = qe;
            redQ[warp * 64 + o0 + 1] = qo;
        }
    }
    __syncthreads();
    if (t < 64) {
        float S = 0.f, Q = 0.f;
#pragma unroll
        for (int ww = 0; ww < 8; ++ww) { S += redS[ww * 64 + t]; Q += redQ[ww * 64 + t]; }
        g_partS[t * 256 + bid] = S;
        g_partQ[t * 256 + bid] = Q;
    }
}

// -------------------- Phase 2: tiny partial reduce --------------------
__global__ __launch_bounds__(256)
void stats2_kernel()
{
    const int o = blockIdx.x;
    const int t = threadIdx.x;
    float s = g_partS[o * 256 + t];
    float q = g_partQ[o * 256 + t];
#pragma unroll
    for (int off = 16; off; off >>= 1) {
        s += __shfl_xor_sync(0xffffffffu, s, off);
        q += __shfl_xor_sync(0xffffffffu, q, off);
    }
    __shared__ float shs[8], shq[8];
    if ((t & 31) == 0) { shs[t >> 5] = s; shq[t >> 5] = q; }
    __syncthreads();
    if (t < 8) {
        s = shs[t]; q = shq[t];
#pragma unroll
        for (int off = 4; off; off >>= 1) {
            s += __shfl_xor_sync(0xffu, s, off);
            q += __shfl_xor_sync(0xffu, q, off);
        }
        if (t == 0) { g_sum[o] = s; g_sumsq[o] = q; }
    }
}

// ------------- Phase 3: BN normalize + ReLU + layout transpose -------------
__global__ __launch_bounds__(256)
void norm_kernel(float* __restrict__ out,
                 const float* __restrict__ gamma,
                 const float* __restrict__ beta)
{
    __shared__ float tile[32][65];
    const int i = blockIdx.x;
    const int o = blockIdx.y;
    const int t = threadIdx.x;

    for (int idx = t; idx < 32 * 64; idx += 256) {
        const int jj = idx >> 6;
        const int bb = idx & 63;
        tile[jj][bb] = g_yt[((size_t)o * POS + i * 32 + jj) * B_ + bb];
    }

    const float invN  = 1.f / (float)(POS * B_);
    const float mean  = g_sum[o] * invN;
    const float var   = g_sumsq[o] * invN - mean * mean;
    const float scale = __ldg(gamma + o) * rsqrtf(var + 1e-5f);
    const float shift = __ldg(beta + o) - mean * scale;
    __syncthreads();

    for (int idx = t; idx < 32 * 64; idx += 256) {
        const int bb = idx >> 5;
        const int jj = idx & 31;
        const float v = tile[jj][bb] * scale + shift;
        out[(((size_t)bb * COUT + o) * IMG + i) * IMG + jj] = fmaxf(v, 0.f);
    }
}

// ---------------------------------------------------------------------------
extern "C" void kernel_launch(void* const* d_in, const int* in_sizes, int n_in,
                              void* d_out, int out_size)
{
    const float* x     = (const float*)d_in[0];
    const float* w     = (const float*)d_in[1];
    const float* bias  = (const float*)d_in[2];
    const float* gamma = (const float*)d_in[3];
    const float* beta  = (const float*)d_in[4];
    float* out = (float*)d_out;

    cudaFuncSetAttribute(ll_mma_kernel,
                         cudaFuncAttributeMaxDynamicSharedMemorySize, SMEM_BYTES);
    ll_mma_kernel<<<256, 256, SMEM_BYTES>>>(x, w, bias);
    stats2_kernel<<<COUT, 256>>>();
    dim3 g3(IMG, COUT);
    norm_kernel<<<g3, 256>>>(out, gamma, beta);
}

// round 10
// speedup vs baseline: 3.8800x; 1.0093x over previous
#include <cuda_runtime.h>
#include <cstdint>

#define B_      64
#define CIN     64
#define COUT    64
#define IMG     32
#define POS     1024
#define CCH     2                 // channels per chunk
#define NCH     32                // 64 / 2
#define WSTRIDE 76                // floats per o-row in W stage (2*36 + 4 pad)
#define WBUF_F  (64 * WSTRIDE)    // 4864 floats per W buffer (x3 ring)
#define XSTRIDE 12                // floats per (g,b) row in X stage (8 used)
#define XBUF_F  (6 * 64 * XSTRIDE) // 4608 floats per X buffer (x2)
#define XBASE_F (3 * WBUF_F)      // 14592
#define SMEM_F  (XBASE_F + 2 * XBUF_F)   // 23808 floats
#define SMEM_BYTES (SMEM_F * 4)          // 95232

__device__ float g_yt[(size_t)COUT * POS * B_];
__device__ float g_partS[COUT * 256];
__device__ float g_partQ[COUT * 256];
__device__ float g_sum[COUT];
__device__ float g_sumsq[COUT];

__device__ __forceinline__ uint32_t to_tf32(float f) {
    uint32_t r;
    asm("cvt.rna.tf32.f32 %0, %1;" : "=r"(r) : "f"(f));
    return r;
}
__device__ __forceinline__ void mma8(float* c, const uint32_t* a,
                                     uint32_t b0, uint32_t b1) {
    asm volatile(
        "mma.sync.aligned.m16n8k8.row.col.f32.tf32.tf32.f32 "
        "{%0,%1,%2,%3}, {%4,%5,%6,%7}, {%8,%9}, {%0,%1,%2,%3};"
        : "+f"(c[0]), "+f"(c[1]), "+f"(c[2]), "+f"(c[3])
        : "r"(a[0]), "r"(a[1]), "r"(a[2]), "r"(a[3]), "r"(b0), "r"(b1));
}
__device__ __forceinline__ uint32_t sptr(const void* p) {
    uint32_t a;
    asm("{ .reg .u64 t; cvta.to.shared.u64 t, %1; cvt.u32.u64 %0, t; }" : "=r"(a) : "l"(p));
    return a;
}
__device__ __forceinline__ void cp16(uint32_t dst, const void* src) {
    asm volatile("cp.async.cg.shared.global [%0], [%1], 16;"
                 :: "r"(dst), "l"(src) : "memory");
}
#define CP_COMMIT() asm volatile("cp.async.commit_group;" ::: "memory")
#define CP_WAIT(N)  asm volatile("cp.async.wait_group %0;" :: "n"(N) : "memory")

// issue cp.async for one chunk of weights (128 granules x 9 float4) + commit
__device__ __forceinline__ void stage_w(const float* __restrict__ w,
                                        int c0, int posb, int t, uint32_t wdst)
{
    for (int f = t; f < 1152; f += 256) {
        const int go = f / 9;
        const int r  = f - go * 9;
        const int o  = go >> 1, cl = go & 1;
        const float* src = w + ((size_t)(o * CIN + c0 + cl) * POS + posb) * 9 + r * 4;
        cp16(wdst + (uint32_t)((o * WSTRIDE + cl * 36 + r * 4) * 4), src);
    }
    CP_COMMIT();
}

// guarded x loads for one chunk into registers (6 float2 / thread)
__device__ __forceinline__ void load_x(const float* __restrict__ x,
                                       int c0, int i, int j0, int t, float2* rx)
{
#pragma unroll
    for (int l = 0; l < 6; ++l) {
        const int f     = t + l * 256;
        const int q     = f & 3;
        const int rowid = f >> 2;
        const int b     = rowid & 63;
        const int g     = rowid >> 6;      // cl*3+u
        const int cl    = (g >= 3);
        const int u     = g - cl * 3;
        const int row   = i - 1 + u;
        const int col   = j0 - 2 + 2 * q;
        float2 v = make_float2(0.f, 0.f);
        const bool ok = ((unsigned)row < IMG) &&
                        !(q == 0 && j0 == 0) && !(q == 3 && j0 == 28);
        if (ok)
            v = *(const float2*)(x + ((size_t)(b * CIN + c0 + cl) * IMG + row) * IMG + col);
        rx[l] = v;
    }
}

// unconditional STS of prefetched x registers, pre-converted to tf32 bits
__device__ __forceinline__ void store_x(uint32_t* xbuf, int t, const float2* rx)
{
#pragma unroll
    for (int l = 0; l < 6; ++l) {
        const int f     = t + l * 256;
        const int q     = f & 3;
        const int rowid = f >> 2;
        uint2 e;
        e.x = to_tf32(rx[l].x);
        e.y = to_tf32(rx[l].y);
        *(uint2*)(xbuf + rowid * XSTRIDE + 2 * q) = e;
    }
}

// ---------------- Phase 1: pipelined tf32 mma.sync GEMM ----------------
__global__ __launch_bounds__(256, 2)
void ll_mma_kernel(const float* __restrict__ x,
                   const float* __restrict__ w,
                   const float* __restrict__ bias)
{
    extern __shared__ float smem[];
    uint32_t* smu = (uint32_t*)smem;
    const uint32_t sbase = sptr(smem);

    const int bid  = blockIdx.x;
    const int i    = bid >> 3;
    const int j0   = (bid & 7) << 2;
    const int posb = i * 32 + j0;
    const int t    = threadIdx.x;
    const int lane = t & 31;
    const int warp = t >> 5;
    const int jj   = warp >> 1;
    const int half = warp & 1;
    const int grp  = lane >> 2;
    const int tig  = lane & 3;

    // ---- hoisted per-ks fragment offsets (chunk-invariant; round-6 math) ----
    int xo1a[3], xo2a[3], wo1a[3], wo2a[3];
    bool v1a[3];
#pragma unroll
    for (int ks = 0; ks < 3; ++ks) {
        const int k1 = ks * 8 + tig;
        v1a[ks] = (ks < 2) || (tig < 2);
        {
            const int kk = v1a[ks] ? k1 : 0;     // dummy safe index when invalid
            const int cl = (kk >= 9) ? 1 : 0;
            const int r  = kk - cl * 9;
            const int u  = r / 3, vv = r - u * 3;
            xo1a[ks] = (cl * 3 + u) * 768 + jj + vv + 1;
            wo1a[ks] = cl * 36 + jj * 9 + r;
        }
        if (ks < 2) {
            const int k2 = k1 + 4;
            const int cl = (k2 >= 9) ? 1 : 0;
            const int r  = k2 - cl * 9;
            const int u  = r / 3, vv = r - u * 3;
            xo2a[ks] = (cl * 3 + u) * 768 + jj + vv + 1;
            wo2a[ks] = cl * 36 + jj * 9 + r;
        } else { xo2a[ks] = 0; wo2a[ks] = 0; }
    }

    float acc[2][8][4];
#pragma unroll
    for (int mt = 0; mt < 2; ++mt)
#pragma unroll
        for (int nt = 0; nt < 8; ++nt)
#pragma unroll
            for (int q = 0; q < 4; ++q) acc[mt][nt][q] = 0.f;

    float2 rx[6];

    // ---- prologue: W(0)->buf0, W(1)->buf1 (cp.async), X(0)->X0 (regs+STS)
    stage_w(w, 0, posb, t, sbase);
    stage_w(w, CCH, posb, t, sbase + (uint32_t)(WBUF_F * 4));
    load_x(x, 0, i, j0, t, rx);
    store_x(smu + XBASE_F, t, rx);
    CP_WAIT(1);          // W(0) complete
    __syncthreads();

    int wb = 0;          // W ring index of current chunk
#pragma unroll 2
    for (int ch = 0; ch < NCH; ++ch) {
        const int  xb = ch & 1;
        const bool hx = (ch + 1 < NCH);
        const bool hw = (ch + 2 < NCH);

        if (hx) load_x(x, (ch + 1) * CCH, i, j0, t, rx);   // LDG prefetch

        const float*    Wb = smem + wb * WBUF_F;
        const uint32_t* Xb = smu + XBASE_F + xb * XBUF_F;

#pragma unroll
        for (int ks = 0; ks < 3; ++ks) {
            const bool v1  = v1a[ks];
            const int  xo1 = xo1a[ks], wo1 = wo1a[ks];
            const int  xo2 = xo2a[ks], wo2 = wo2a[ks];

            uint32_t a[2][4];
#pragma unroll
            for (int mt = 0; mt < 2; ++mt) {
                const int br = half * 32 + mt * 16 + grp;
                a[mt][0] = v1 ? Xb[xo1 + br * XSTRIDE]       : 0u;
                a[mt][1] = v1 ? Xb[xo1 + (br + 8) * XSTRIDE] : 0u;
                a[mt][2] = (ks < 2) ? Xb[xo2 + br * XSTRIDE]       : 0u;
                a[mt][3] = (ks < 2) ? Xb[xo2 + (br + 8) * XSTRIDE] : 0u;
            }
#pragma unroll
            for (int nt = 0; nt < 8; ++nt) {
                const int o = nt * 8 + grp;
                const float bf0 = v1 ? Wb[o * WSTRIDE + wo1] : 0.f;
                const float bf1 = (ks < 2) ? Wb[o * WSTRIDE + wo2] : 0.f;
                const uint32_t b0 = to_tf32(bf0);
                const uint32_t b1 = to_tf32(bf1);
                mma8(acc[0][nt], a[0], b0, b1);
                mma8(acc[1][nt], a[1], b0, b1);
            }

            // interleave staging with compute phases
            if (ks == 0) {
                int wb2 = wb + 2; if (wb2 >= 3) wb2 -= 3;
                if (hw) stage_w(w, (ch + 2) * CCH, posb, t,
                                sbase + (uint32_t)(wb2 * WBUF_F * 4));
                else    CP_COMMIT();          // keep group count uniform
            } else if (ks == 1) {
                if (hx) store_x(smu + XBASE_F + (xb ^ 1) * XBUF_F, t, rx);
            }
        }

        CP_WAIT(1);        // W(ch+1) complete (its group committed last iter)
        __syncthreads();   // X(ch+1) STS visible; all reads of old bufs done
        wb = (wb + 1 == 3) ? 0 : wb + 1;
    }
    CP_WAIT(0);

    // ---- epilogue: bias + store yt + fused per-block BN partials ----
    const int pos = posb + jj;
    float* redS = smem;
    float* redQ = smem + 512;

#pragma unroll
    for (int nt = 0; nt < 8; ++nt) {
        const int o0 = nt * 8 + tig * 2;
        const float bs0 = __ldg(bias + o0 * POS + pos);
        const float bs1 = __ldg(bias + (o0 + 1) * POS + pos);
        float y[2][4];
#pragma unroll
        for (int mt = 0; mt < 2; ++mt) {
            y[mt][0] = acc[mt][nt][0] + bs0;
            y[mt][1] = acc[mt][nt][1] + bs1;
            y[mt][2] = acc[mt][nt][2] + bs0;
            y[mt][3] = acc[mt][nt][3] + bs1;
            const int b = half * 32 + mt * 16 + grp;
            g_yt[((size_t)o0 * POS + pos) * B_ + b]           = y[mt][0];
            g_yt[((size_t)(o0 + 1) * POS + pos) * B_ + b]     = y[mt][1];
            g_yt[((size_t)o0 * POS + pos) * B_ + b + 8]       = y[mt][2];
            g_yt[((size_t)(o0 + 1) * POS + pos) * B_ + b + 8] = y[mt][3];
        }
        float se = y[0][0] + y[0][2] + y[1][0] + y[1][2];
        float so = y[0][1] + y[0][3] + y[1][1] + y[1][3];
        float qe = y[0][0]*y[0][0] + y[0][2]*y[0][2] + y[1][0]*y[1][0] + y[1][2]*y[1][2];
        float qo = y[0][1]*y[0][1] + y[0][3]*y[0][3] + y[1][1]*y[1][1] + y[1][3]*y[1][3];
#pragma unroll
        for (int off = 4; off <= 16; off <<= 1) {
            se += __shfl_xor_sync(0xffffffffu, se, off);
            so += __shfl_xor_sync(0xffffffffu, so, off);
            qe += __shfl_xor_sync(0xffffffffu, qe, off);
            qo += __shfl_xor_sync(0xffffffffu, qo, off);
        }
        if (grp == 0) {
            redS[warp * 64 + o0]     = se;
            redS[warp * 64 + o0 + 1] = so;
            redQ[warp * 64 + o0]     = qe;
            redQ[warp * 64 + o0 + 1] = qo;
        }
    }
    __syncthreads();
    if (t < 64) {
        float S = 0.f, Q = 0.f;
#pragma unroll
        for (int ww = 0; ww < 8; ++ww) { S += redS[ww * 64 + t]; Q += redQ[ww * 64 + t]; }
        g_partS[t * 256 + bid] = S;
        g_partQ[t * 256 + bid] = Q;
    }
}

// -------------------- Phase 2: tiny partial reduce --------------------
__global__ __launch_bounds__(256)
void stats2_kernel()
{
    const int o = blockIdx.x;
    const int t = threadIdx.x;
    float s = g_partS[o * 256 + t];
    float q = g_partQ[o * 256 + t];
#pragma unroll
    for (int off = 16; off; off >>= 1) {
        s += __shfl_xor_sync(0xffffffffu, s, off);
        q += __shfl_xor_sync(0xffffffffu, q, off);
    }
    __shared__ float shs[8], shq[8];
    if ((t & 31) == 0) { shs[t >> 5] = s; shq[t >> 5] = q; }
    __syncthreads();
    if (t < 8) {
        s = shs[t]; q = shq[t];
#pragma unroll
        for (int off = 4; off; off >>= 1) {
            s += __shfl_xor_sync(0xffu, s, off);
            q += __shfl_xor_sync(0xffu, q, off);
        }
        if (t == 0) { g_sum[o] = s; g_sumsq[o] = q; }
    }
}

// ------------- Phase 3: BN normalize + ReLU + layout transpose -------------
__global__ __launch_bounds__(256)
void norm_kernel(float* __restrict__ out,
                 const float* __restrict__ gamma,
                 const float* __restrict__ beta)
{
    __shared__ float tile[32][65];
    const int i = blockIdx.x;
    const int o = blockIdx.y;
    const int t = threadIdx.x;

    for (int idx = t; idx < 32 * 64; idx += 256) {
        const int jj = idx >> 6;
        const int bb = idx & 63;
        tile[jj][bb] = g_yt[((size_t)o * POS + i * 32 + jj) * B_ + bb];
    }
    const float invN  = 1.f / (float)(POS * B_);
    const float mean  = g_sum[o] * invN;
    const float var   = g_sumsq[o] * invN - mean * mean;
    const float scale = __ldg(gamma + o) * rsqrtf(var + 1e-5f);
    const float shift = __ldg(beta + o) - mean * scale;
    __syncthreads();

    for (int idx = t; idx < 32 * 64; idx += 256) {
        const int bb = idx >> 5;
        const int jj = idx & 31;
        const float v = tile[jj][bb] * scale + shift;
        out[(((size_t)bb * COUT + o) * IMG + i) * IMG + jj] = fmaxf(v, 0.f);
    }
}

// ---------------------------------------------------------------------------
extern "C" void kernel_launch(void* const* d_in, const int* in_sizes, int n_in,
                              void* d_out, int out_size)
{
    const float* x     = (const float*)d_in[0];
    const float* w     = (const float*)d_in[1];
    const float* bias  = (const float*)d_in[2];
    const float* gamma = (const float*)d_in[3];
    const float* beta  = (const float*)d_in[4];
    float* out = (float*)d_out;

    cudaFuncSetAttribute(ll_mma_kernel,
                         cudaFuncAttributeMaxDynamicSharedMemorySize, SMEM_BYTES);
    ll_mma_kernel<<<256, 256, SMEM_BYTES>>>(x, w, bias);
    stats2_kernel<<<COUT, 256>>>();
    dim3 g3(IMG, COUT);
    norm_kernel<<<g3, 256>>>(out, gamma, beta);
}